// round 3
// baseline (speedup 1.0000x reference)
#include <cuda_runtime.h>

// Problem constants
#define CDIM   256
#define HEADS  8
#define HD     32
#define SDIM   40          // H == W == D == 40
#define PDIM   64000       // H*W*D
#define BATCH  2

// Scratch (device globals; no allocation)
__device__ float g_q[BATCH * CDIM * PDIM];
__device__ float g_k[BATCH * CDIM * PDIM];
__device__ float g_v[BATCH * CDIM * PDIM];
__device__ float g_attn[BATCH * CDIM * PDIM];

// ---------------------------------------------------------------------------
// Kernel 1: fused QKV 1x1x1 conv (GEMM). For each batch b:
//   q[o,p] = sum_c wq[o,c] * x[c,p] + bq[o]   (same for k, v)
// M = 256 (o), K = 256 (c), N = 64000 (p). Tile 64x64, micro 4x4, TK = 16.
// ---------------------------------------------------------------------------
__global__ __launch_bounds__(256) void qkv_gemm(
    const float* __restrict__ x,
    const float* __restrict__ wq, const float* __restrict__ bq,
    const float* __restrict__ wk, const float* __restrict__ bk,
    const float* __restrict__ wv, const float* __restrict__ bv)
{
    __shared__ __align__(16) float sX [16][64];
    __shared__ __align__(16) float sWq[16][68];
    __shared__ __align__(16) float sWk[16][68];
    __shared__ __align__(16) float sWv[16][68];

    const int b   = blockIdx.z;
    const int m0  = blockIdx.y * 64;
    const int n0  = blockIdx.x * 64;
    const int tid = threadIdx.x;
    const int tx  = tid & 15;       // 0..15 -> n micro-tile
    const int ty  = tid >> 4;       // 0..15 -> m micro-tile

    const float* xb = x + (size_t)b * CDIM * PDIM;

    float accq[4][4] = {};
    float acck[4][4] = {};
    float accv[4][4] = {};

    for (int k0 = 0; k0 < CDIM; k0 += 16) {
        #pragma unroll
        for (int i = 0; i < 4; i++) {
            int e  = tid + i * 256;
            int kr = e >> 6;
            int nc = e & 63;
            sX[kr][nc] = xb[(k0 + kr) * PDIM + n0 + nc];
        }
        #pragma unroll
        for (int i = 0; i < 4; i++) {
            int e    = tid + i * 256;
            int m    = e >> 4;
            int kk   = e & 15;
            int gidx = (m0 + m) * CDIM + k0 + kk;
            sWq[kk][m] = wq[gidx];
            sWk[kk][m] = wk[gidx];
            sWv[kk][m] = wv[gidx];
        }
        __syncthreads();

        #pragma unroll
        for (int kk = 0; kk < 16; kk++) {
            float4 b4 = *(const float4*)&sX [kk][tx * 4];
            float4 q4 = *(const float4*)&sWq[kk][ty * 4];
            float4 k4 = *(const float4*)&sWk[kk][ty * 4];
            float4 v4 = *(const float4*)&sWv[kk][ty * 4];
            float xr[4] = {b4.x, b4.y, b4.z, b4.w};
            float qr[4] = {q4.x, q4.y, q4.z, q4.w};
            float kr[4] = {k4.x, k4.y, k4.z, k4.w};
            float vr[4] = {v4.x, v4.y, v4.z, v4.w};
            #pragma unroll
            for (int i = 0; i < 4; i++)
                #pragma unroll
                for (int j = 0; j < 4; j++) {
                    accq[i][j] = fmaf(qr[i], xr[j], accq[i][j]);
                    acck[i][j] = fmaf(kr[i], xr[j], acck[i][j]);
                    accv[i][j] = fmaf(vr[i], xr[j], accv[i][j]);
                }
        }
        __syncthreads();
    }

    #pragma unroll
    for (int i = 0; i < 4; i++) {
        const int m = m0 + ty * 4 + i;
        const float biq = bq[m];
        const float bik = bk[m];
        const float biv = bv[m];
        const size_t row = ((size_t)b * CDIM + m) * PDIM + n0 + tx * 4;
        float4 oq = {accq[i][0] + biq, accq[i][1] + biq, accq[i][2] + biq, accq[i][3] + biq};
        float4 ok = {acck[i][0] + bik, acck[i][1] + bik, acck[i][2] + bik, acck[i][3] + bik};
        float4 ov = {accv[i][0] + biv, accv[i][1] + biv, accv[i][2] + biv, accv[i][3] + biv};
        *(float4*)&g_q[row] = oq;
        *(float4*)&g_k[row] = ok;
        *(float4*)&g_v[row] = ov;
    }
}

// ---------------------------------------------------------------------------
// Kernel 2: attention. All three reference "branches" are bitwise identical
// (reshape of equal dims), so compute one and scale by 3.
// One block per (b*head, hd-channel, s1): a contiguous 40x40 fp32 slab.
//   S = softmax_row(Q K^T * hd^-0.5);  O = 3 * (S V)
// ---------------------------------------------------------------------------
__global__ __launch_bounds__(256) void attn_kernel()
{
    __shared__ float sQ[40][41];
    __shared__ float sK[40][41];
    __shared__ float sV[40][41];
    __shared__ float sS[40][41];

    const int s1  = blockIdx.x;   // 0..39
    const int c   = blockIdx.y;   // 0..31 (within-head channel)
    const int bh  = blockIdx.z;   // 0..15 (b*HEADS + head)
    const int tid = threadIdx.x;

    // (bh*HD + c) == b*CDIM + head*HD + c  since bh = b*8 + head, HD = 32
    const size_t base = (size_t)(bh * HD + c) * PDIM + s1 * 1600;

    for (int e = tid; e < 1600; e += 256) {
        int r  = e / 40;
        int cc = e - r * 40;
        sQ[r][cc] = g_q[base + e];
        sK[r][cc] = g_k[base + e];
        sV[r][cc] = g_v[base + e];
    }
    __syncthreads();

    const float scale = 0.17677669529663687f;   // 32^-0.5

    // S = Q K^T * scale   (4x4 register tiles, 100 active threads)
    if (tid < 100) {
        const int i0 = (tid / 10) * 4;
        const int j0 = (tid % 10) * 4;
        float acc[4][4] = {};
        #pragma unroll 8
        for (int k = 0; k < 40; k++) {
            float qv[4], kv[4];
            #pragma unroll
            for (int a = 0; a < 4; a++) { qv[a] = sQ[i0 + a][k]; kv[a] = sK[j0 + a][k]; }
            #pragma unroll
            for (int a = 0; a < 4; a++)
                #pragma unroll
                for (int bb = 0; bb < 4; bb++)
                    acc[a][bb] = fmaf(qv[a], kv[bb], acc[a][bb]);
        }
        #pragma unroll
        for (int a = 0; a < 4; a++)
            #pragma unroll
            for (int bb = 0; bb < 4; bb++)
                sS[i0 + a][j0 + bb] = acc[a][bb] * scale;
    }
    __syncthreads();

    // row softmax (40 rows; one thread per row is plenty here)
    if (tid < 40) {
        float mx = -1e30f;
        #pragma unroll 8
        for (int j = 0; j < 40; j++) mx = fmaxf(mx, sS[tid][j]);
        float sum = 0.0f;
        #pragma unroll 8
        for (int j = 0; j < 40; j++) {
            float ev = __expf(sS[tid][j] - mx);
            sS[tid][j] = ev;
            sum += ev;
        }
        const float inv = 1.0f / sum;
        #pragma unroll 8
        for (int j = 0; j < 40; j++) sS[tid][j] *= inv;
    }
    __syncthreads();

    // O = 3 * (S V)
    if (tid < 100) {
        const int i0 = (tid / 10) * 4;
        const int j0 = (tid % 10) * 4;
        float acc[4][4] = {};
        #pragma unroll 8
        for (int k = 0; k < 40; k++) {
            float av[4], vv[4];
            #pragma unroll
            for (int a = 0; a < 4; a++) { av[a] = sS[i0 + a][k]; vv[a] = sV[k][j0 + a]; }
            #pragma unroll
            for (int a = 0; a < 4; a++)
                #pragma unroll
                for (int bb = 0; bb < 4; bb++)
                    acc[a][bb] = fmaf(av[a], vv[bb], acc[a][bb]);
        }
        #pragma unroll
        for (int a = 0; a < 4; a++) {
            float4 o = {3.0f * acc[a][0], 3.0f * acc[a][1],
                        3.0f * acc[a][2], 3.0f * acc[a][3]};
            *(float4*)&g_attn[base + (size_t)(i0 + a) * 40 + j0] = o;
        }
    }
}

// ---------------------------------------------------------------------------
// Kernel 3: output projection GEMM: out = wp @ attn + bp
// ---------------------------------------------------------------------------
__global__ __launch_bounds__(256) void proj_gemm(
    const float* __restrict__ wp, const float* __restrict__ bp,
    float* __restrict__ out)
{
    __shared__ __align__(16) float sX[16][64];
    __shared__ __align__(16) float sW[16][68];

    const int b   = blockIdx.z;
    const int m0  = blockIdx.y * 64;
    const int n0  = blockIdx.x * 64;
    const int tid = threadIdx.x;
    const int tx  = tid & 15;
    const int ty  = tid >> 4;

    const float* xb = g_attn + (size_t)b * CDIM * PDIM;

    float acc[4][4] = {};

    for (int k0 = 0; k0 < CDIM; k0 += 16) {
        #pragma unroll
        for (int i = 0; i < 4; i++) {
            int e  = tid + i * 256;
            int kr = e >> 6;
            int nc = e & 63;
            sX[kr][nc] = xb[(k0 + kr) * PDIM + n0 + nc];
        }
        #pragma unroll
        for (int i = 0; i < 4; i++) {
            int e  = tid + i * 256;
            int m  = e >> 4;
            int kk = e & 15;
            sW[kk][m] = wp[(m0 + m) * CDIM + k0 + kk];
        }
        __syncthreads();

        #pragma unroll
        for (int kk = 0; kk < 16; kk++) {
            float4 b4 = *(const float4*)&sX[kk][tx * 4];
            float4 a4 = *(const float4*)&sW[kk][ty * 4];
            float xr[4] = {b4.x, b4.y, b4.z, b4.w};
            float ar[4] = {a4.x, a4.y, a4.z, a4.w};
            #pragma unroll
            for (int i = 0; i < 4; i++)
                #pragma unroll
                for (int j = 0; j < 4; j++)
                    acc[i][j] = fmaf(ar[i], xr[j], acc[i][j]);
        }
        __syncthreads();
    }

    #pragma unroll
    for (int i = 0; i < 4; i++) {
        const int m = m0 + ty * 4 + i;
        const float bi = bp[m];
        const size_t row = ((size_t)b * CDIM + m) * PDIM + n0 + tx * 4;
        float4 o = {acc[i][0] + bi, acc[i][1] + bi, acc[i][2] + bi, acc[i][3] + bi};
        *(float4*)&out[row] = o;
    }
}

// ---------------------------------------------------------------------------
extern "C" void kernel_launch(void* const* d_in, const int* in_sizes, int n_in,
                              void* d_out, int out_size)
{
    const float* x  = (const float*)d_in[0];
    const float* wq = (const float*)d_in[1];
    const float* bq = (const float*)d_in[2];
    const float* wk = (const float*)d_in[3];
    const float* bk = (const float*)d_in[4];
    const float* wv = (const float*)d_in[5];
    const float* bv = (const float*)d_in[6];
    const float* wp = (const float*)d_in[7];
    const float* bp = (const float*)d_in[8];
    float* out = (float*)d_out;

    dim3 gemm_grid(PDIM / 64, CDIM / 64, BATCH);   // 1000 x 4 x 2
    qkv_gemm<<<gemm_grid, 256>>>(x, wq, bq, wk, bk, wv, bv);

    dim3 attn_grid(SDIM, HD, BATCH * HEADS);        // 40 x 32 x 16
    attn_kernel<<<attn_grid, 256>>>();

    proj_gemm<<<gemm_grid, 256>>>(wp, bp, out);
}

// round 5
// speedup vs baseline: 1.7021x; 1.7021x over previous
#include <cuda_runtime.h>
#include <cstdint>

// Problem constants
#define CDIM   256
#define HEADS  8
#define HD     32
#define SDIM   40          // H == W == D == 40
#define PDIM   64000       // H*W*D
#define BATCH  2

// GEMM tiling
#define BM 64
#define BN 128
#define BK 16
#define XPAD 8             // BN+8 = 136; 136 % 32 == 8 -> conflict-free frag gathers
#define WPAD 8             // BM+8 = 72;   72 % 32 == 8

// Scratch (device globals; no allocation)
__device__ float g_q[BATCH * CDIM * PDIM];
__device__ float g_k[BATCH * CDIM * PDIM];
__device__ float g_v[BATCH * CDIM * PDIM];
__device__ float g_attn[BATCH * CDIM * PDIM];

// cvt.rna.tf32.f32 requires a .b32 destination -> return raw bits in uint32_t
__device__ __forceinline__ uint32_t to_tf32(float x) {
    uint32_t r;
    asm("cvt.rna.tf32.f32 %0, %1;" : "=r"(r) : "f"(x));
    return r;
}

__device__ __forceinline__ void mma_tf32(float* d, const uint32_t* a, const uint32_t* b) {
    asm volatile(
        "mma.sync.aligned.m16n8k8.row.col.f32.tf32.tf32.f32 "
        "{%0,%1,%2,%3}, {%4,%5,%6,%7}, {%8,%9}, {%0,%1,%2,%3};"
        : "+f"(d[0]), "+f"(d[1]), "+f"(d[2]), "+f"(d[3])
        : "r"(a[0]), "r"(a[1]), "r"(a[2]), "r"(a[3]), "r"(b[0]), "r"(b[1]));
}

// ---------------------------------------------------------------------------
// Kernel 1: fused QKV 1x1x1 conv as TF32 tensor-core GEMM.
//   q[o,p] = sum_c wq[o,c]*x[c,p] + bq[o]   (same for k, v; shared X tile)
// ---------------------------------------------------------------------------
__global__ __launch_bounds__(256) void qkv_gemm(
    const float* __restrict__ x,
    const float* __restrict__ wq, const float* __restrict__ bq,
    const float* __restrict__ wk, const float* __restrict__ bk,
    const float* __restrict__ wv, const float* __restrict__ bv)
{
    __shared__ __align__(16) uint32_t sX [BK][BN + XPAD];
    __shared__ __align__(16) uint32_t sWq[BK][BM + WPAD];
    __shared__ __align__(16) uint32_t sWk[BK][BM + WPAD];
    __shared__ __align__(16) uint32_t sWv[BK][BM + WPAD];

    const int b    = blockIdx.z;
    const int m0   = blockIdx.y * BM;
    const int n0   = blockIdx.x * BN;
    const int tid  = threadIdx.x;
    const int warp = tid >> 5;
    const int lane = tid & 31;
    const int wm   = warp >> 2;          // 0..1
    const int wn   = warp & 3;           // 0..3
    const int g    = lane >> 2;          // group id 0..7
    const int t    = lane & 3;           // thread-in-group 0..3

    const float* xb = x + (size_t)b * CDIM * PDIM;

    float accq[2][4][4] = {};
    float acck[2][4][4] = {};
    float accv[2][4][4] = {};

    // W loader indices: m spans 64 consecutive per 64 threads -> conflict-free STS
    const int wl_m  = tid & 63;          // 0..63
    const int wl_kk = (tid >> 6) << 2;   // 0,4,8,12

    for (int k0 = 0; k0 < CDIM; k0 += BK) {
        // Load X tile (16x128), 2 float4 per thread, coalesced
        #pragma unroll
        for (int i = 0; i < 2; i++) {
            int idx = tid + i * 256;
            int kr  = idx >> 5;
            int nc  = (idx & 31) * 4;
            float4 xv = *(const float4*)&xb[(size_t)(k0 + kr) * PDIM + n0 + nc];
            uint4 xt = {to_tf32(xv.x), to_tf32(xv.y), to_tf32(xv.z), to_tf32(xv.w)};
            *(uint4*)&sX[kr][nc] = xt;
        }
        // Load W tiles (64x16 each), transpose into [k][m]
        {
            const size_t widx = (size_t)(m0 + wl_m) * CDIM + k0 + wl_kk;
            float4 q4 = *(const float4*)&wq[widx];
            float4 k4 = *(const float4*)&wk[widx];
            float4 v4 = *(const float4*)&wv[widx];
            sWq[wl_kk + 0][wl_m] = to_tf32(q4.x);
            sWq[wl_kk + 1][wl_m] = to_tf32(q4.y);
            sWq[wl_kk + 2][wl_m] = to_tf32(q4.z);
            sWq[wl_kk + 3][wl_m] = to_tf32(q4.w);
            sWk[wl_kk + 0][wl_m] = to_tf32(k4.x);
            sWk[wl_kk + 1][wl_m] = to_tf32(k4.y);
            sWk[wl_kk + 2][wl_m] = to_tf32(k4.z);
            sWk[wl_kk + 3][wl_m] = to_tf32(k4.w);
            sWv[wl_kk + 0][wl_m] = to_tf32(v4.x);
            sWv[wl_kk + 1][wl_m] = to_tf32(v4.y);
            sWv[wl_kk + 2][wl_m] = to_tf32(v4.z);
            sWv[wl_kk + 3][wl_m] = to_tf32(v4.w);
        }
        __syncthreads();

        #pragma unroll
        for (int ks = 0; ks < BK; ks += 8) {
            // B fragments from X: 4 n-subtiles
            uint32_t bf[4][2];
            #pragma unroll
            for (int ni = 0; ni < 4; ni++) {
                int ncol = wn * 32 + ni * 8 + g;
                bf[ni][0] = sX[ks + t    ][ncol];
                bf[ni][1] = sX[ks + t + 4][ncol];
            }
            // For each weight matrix: A fragments + 8 MMAs
            #pragma unroll
            for (int mat = 0; mat < 3; mat++) {
                const uint32_t (*sW)[BM + WPAD] = (mat == 0) ? sWq : (mat == 1) ? sWk : sWv;
                float (*acc)[4][4]              = (mat == 0) ? accq : (mat == 1) ? acck : accv;
                #pragma unroll
                for (int mi = 0; mi < 2; mi++) {
                    int r = wm * 32 + mi * 16 + g;
                    uint32_t af[4];
                    af[0] = sW[ks + t    ][r    ];
                    af[1] = sW[ks + t    ][r + 8];
                    af[2] = sW[ks + t + 4][r    ];
                    af[3] = sW[ks + t + 4][r + 8];
                    #pragma unroll
                    for (int ni = 0; ni < 4; ni++)
                        mma_tf32(acc[mi][ni], af, bf[ni]);
                }
            }
        }
        __syncthreads();
    }

    // Epilogue: bias + store (float2 per D-register pair)
    #pragma unroll
    for (int mi = 0; mi < 2; mi++) {
        #pragma unroll
        for (int rr = 0; rr < 2; rr++) {
            const int m  = m0 + wm * 32 + mi * 16 + g + rr * 8;
            const float biq = bq[m], bik = bk[m], biv = bv[m];
            const size_t rowbase = ((size_t)b * CDIM + m) * PDIM;
            #pragma unroll
            for (int ni = 0; ni < 4; ni++) {
                const size_t o = rowbase + n0 + wn * 32 + ni * 8 + t * 2;
                float2 vq = {accq[mi][ni][rr * 2] + biq, accq[mi][ni][rr * 2 + 1] + biq};
                float2 vk = {acck[mi][ni][rr * 2] + bik, acck[mi][ni][rr * 2 + 1] + bik};
                float2 vv = {accv[mi][ni][rr * 2] + biv, accv[mi][ni][rr * 2 + 1] + biv};
                *(float2*)&g_q[o] = vq;
                *(float2*)&g_k[o] = vk;
                *(float2*)&g_v[o] = vv;
            }
        }
    }
}

// ---------------------------------------------------------------------------
// Kernel 2: attention (all three reference branches are bitwise identical
// reshapes since H==W==D, so compute one and scale by 3).
// One block per (b*head, hd-channel, s1): contiguous 40x40 fp32 slab.
// ---------------------------------------------------------------------------
__global__ __launch_bounds__(256) void attn_kernel()
{
    __shared__ float sQ[40][41];
    __shared__ float sK[40][41];
    __shared__ float sV[40][41];
    __shared__ float sS[40][41];

    const int s1  = blockIdx.x;
    const int c   = blockIdx.y;
    const int bh  = blockIdx.z;
    const int tid = threadIdx.x;

    const size_t base = (size_t)(bh * HD + c) * PDIM + s1 * 1600;

    for (int e = tid; e < 1600; e += 256) {
        int r  = e / 40;
        int cc = e - r * 40;
        sQ[r][cc] = g_q[base + e];
        sK[r][cc] = g_k[base + e];
        sV[r][cc] = g_v[base + e];
    }
    __syncthreads();

    const float scale = 0.17677669529663687f;   // 32^-0.5

    if (tid < 100) {
        const int i0 = (tid / 10) * 4;
        const int j0 = (tid % 10) * 4;
        float acc[4][4] = {};
        #pragma unroll 8
        for (int k = 0; k < 40; k++) {
            float qv[4], kv[4];
            #pragma unroll
            for (int a = 0; a < 4; a++) { qv[a] = sQ[i0 + a][k]; kv[a] = sK[j0 + a][k]; }
            #pragma unroll
            for (int a = 0; a < 4; a++)
                #pragma unroll
                for (int bb = 0; bb < 4; bb++)
                    acc[a][bb] = fmaf(qv[a], kv[bb], acc[a][bb]);
        }
        #pragma unroll
        for (int a = 0; a < 4; a++)
            #pragma unroll
            for (int bb = 0; bb < 4; bb++)
                sS[i0 + a][j0 + bb] = acc[a][bb] * scale;
    }
    __syncthreads();

    if (tid < 40) {
        float mx = -1e30f;
        #pragma unroll 8
        for (int j = 0; j < 40; j++) mx = fmaxf(mx, sS[tid][j]);
        float sum = 0.0f;
        #pragma unroll 8
        for (int j = 0; j < 40; j++) {
            float ev = __expf(sS[tid][j] - mx);
            sS[tid][j] = ev;
            sum += ev;
        }
        const float inv = 1.0f / sum;
        #pragma unroll 8
        for (int j = 0; j < 40; j++) sS[tid][j] *= inv;
    }
    __syncthreads();

    if (tid < 100) {
        const int i0 = (tid / 10) * 4;
        const int j0 = (tid % 10) * 4;
        float acc[4][4] = {};
        #pragma unroll 8
        for (int k = 0; k < 40; k++) {
            float av[4], vv[4];
            #pragma unroll
            for (int a = 0; a < 4; a++) { av[a] = sS[i0 + a][k]; vv[a] = sV[k][j0 + a]; }
            #pragma unroll
            for (int a = 0; a < 4; a++)
                #pragma unroll
                for (int bb = 0; bb < 4; bb++)
                    acc[a][bb] = fmaf(av[a], vv[bb], acc[a][bb]);
        }
        #pragma unroll
        for (int a = 0; a < 4; a++) {
            float4 o = {3.0f * acc[a][0], 3.0f * acc[a][1],
                        3.0f * acc[a][2], 3.0f * acc[a][3]};
            *(float4*)&g_attn[base + (size_t)(i0 + a) * 40 + j0] = o;
        }
    }
}

// ---------------------------------------------------------------------------
// Kernel 3: output projection, TF32 tensor-core GEMM: out = wp @ attn + bp
// ---------------------------------------------------------------------------
__global__ __launch_bounds__(256) void proj_gemm(
    const float* __restrict__ wp, const float* __restrict__ bp,
    float* __restrict__ out)
{
    __shared__ __align__(16) uint32_t sX[BK][BN + XPAD];
    __shared__ __align__(16) uint32_t sW[BK][BM + WPAD];

    const int b    = blockIdx.z;
    const int m0   = blockIdx.y * BM;
    const int n0   = blockIdx.x * BN;
    const int tid  = threadIdx.x;
    const int warp = tid >> 5;
    const int lane = tid & 31;
    const int wm   = warp >> 2;
    const int wn   = warp & 3;
    const int g    = lane >> 2;
    const int t    = lane & 3;

    const float* xb = g_attn + (size_t)b * CDIM * PDIM;

    float acc[2][4][4] = {};

    const int wl_m  = tid & 63;
    const int wl_kk = (tid >> 6) << 2;

    for (int k0 = 0; k0 < CDIM; k0 += BK) {
        #pragma unroll
        for (int i = 0; i < 2; i++) {
            int idx = tid + i * 256;
            int kr  = idx >> 5;
            int nc  = (idx & 31) * 4;
            float4 xv = *(const float4*)&xb[(size_t)(k0 + kr) * PDIM + n0 + nc];
            uint4 xt = {to_tf32(xv.x), to_tf32(xv.y), to_tf32(xv.z), to_tf32(xv.w)};
            *(uint4*)&sX[kr][nc] = xt;
        }
        {
            float4 w4 = *(const float4*)&wp[(size_t)(m0 + wl_m) * CDIM + k0 + wl_kk];
            sW[wl_kk + 0][wl_m] = to_tf32(w4.x);
            sW[wl_kk + 1][wl_m] = to_tf32(w4.y);
            sW[wl_kk + 2][wl_m] = to_tf32(w4.z);
            sW[wl_kk + 3][wl_m] = to_tf32(w4.w);
        }
        __syncthreads();

        #pragma unroll
        for (int ks = 0; ks < BK; ks += 8) {
            uint32_t bf[4][2];
            #pragma unroll
            for (int ni = 0; ni < 4; ni++) {
                int ncol = wn * 32 + ni * 8 + g;
                bf[ni][0] = sX[ks + t    ][ncol];
                bf[ni][1] = sX[ks + t + 4][ncol];
            }
            #pragma unroll
            for (int mi = 0; mi < 2; mi++) {
                int r = wm * 32 + mi * 16 + g;
                uint32_t af[4];
                af[0] = sW[ks + t    ][r    ];
                af[1] = sW[ks + t    ][r + 8];
                af[2] = sW[ks + t + 4][r    ];
                af[3] = sW[ks + t + 4][r + 8];
                #pragma unroll
                for (int ni = 0; ni < 4; ni++)
                    mma_tf32(acc[mi][ni], af, bf[ni]);
            }
        }
        __syncthreads();
    }

    #pragma unroll
    for (int mi = 0; mi < 2; mi++) {
        #pragma unroll
        for (int rr = 0; rr < 2; rr++) {
            const int m  = m0 + wm * 32 + mi * 16 + g + rr * 8;
            const float bi = bp[m];
            const size_t rowbase = ((size_t)b * CDIM + m) * PDIM;
            #pragma unroll
            for (int ni = 0; ni < 4; ni++) {
                const size_t o = rowbase + n0 + wn * 32 + ni * 8 + t * 2;
                float2 v = {acc[mi][ni][rr * 2] + bi, acc[mi][ni][rr * 2 + 1] + bi};
                *(float2*)&out[o] = v;
            }
        }
    }
}

// ---------------------------------------------------------------------------
extern "C" void kernel_launch(void* const* d_in, const int* in_sizes, int n_in,
                              void* d_out, int out_size)
{
    const float* x  = (const float*)d_in[0];
    const float* wq = (const float*)d_in[1];
    const float* bq = (const float*)d_in[2];
    const float* wk = (const float*)d_in[3];
    const float* bk = (const float*)d_in[4];
    const float* wv = (const float*)d_in[5];
    const float* bv = (const float*)d_in[6];
    const float* wp = (const float*)d_in[7];
    const float* bp = (const float*)d_in[8];
    float* out = (float*)d_out;

    dim3 gemm_grid(PDIM / BN, CDIM / BM, BATCH);   // 500 x 4 x 2
    qkv_gemm<<<gemm_grid, 256>>>(x, wq, bq, wk, bk, wv, bv);

    dim3 attn_grid(SDIM, HD, BATCH * HEADS);        // 40 x 32 x 16
    attn_kernel<<<attn_grid, 256>>>();

    proj_gemm<<<gemm_grid, 256>>>(wp, bp, out);
}

// round 7
// speedup vs baseline: 1.9946x; 1.1719x over previous
#include <cuda_runtime.h>
#include <cstdint>

// Problem constants
#define CDIM   256
#define HEADS  8
#define HD     32
#define SDIM   40          // H == W == D == 40
#define PDIM   64000       // H*W*D
#define BATCH  2

// GEMM tiling
#define BM 64
#define BN 128
#define BK 16
#define XPAD 8             // stride 136; 136 % 32 == 8 -> conflict-free frag gathers
#define KPAD 4             // W row stride 20; (g*20+t) mod 32 covers 0..31

// Scratch (device globals; no allocation)
__device__ float g_q[BATCH * CDIM * PDIM];
__device__ float g_k[BATCH * CDIM * PDIM];
__device__ float g_v[BATCH * CDIM * PDIM];
__device__ float g_attn[BATCH * CDIM * PDIM];

__device__ __forceinline__ uint32_t to_tf32(float x) {
    uint32_t r;
    asm("cvt.rna.tf32.f32 %0, %1;" : "=r"(r) : "f"(x));
    return r;
}

__device__ __forceinline__ void mma_tf32(float* d, const uint32_t* a, const uint32_t* b) {
    asm volatile(
        "mma.sync.aligned.m16n8k8.row.col.f32.tf32.tf32.f32 "
        "{%0,%1,%2,%3}, {%4,%5,%6,%7}, {%8,%9}, {%0,%1,%2,%3};"
        : "+f"(d[0]), "+f"(d[1]), "+f"(d[2]), "+f"(d[3])
        : "r"(a[0]), "r"(a[1]), "r"(a[2]), "r"(a[3]), "r"(b[0]), "r"(b[1]));
}

__device__ __forceinline__ void cp16(void* smem, const void* gmem) {
    uint32_t sa = (uint32_t)__cvta_generic_to_shared(smem);
    asm volatile("cp.async.ca.shared.global [%0], [%1], 16;" :: "r"(sa), "l"(gmem));
}
__device__ __forceinline__ void cp_commit() { asm volatile("cp.async.commit_group;"); }
template <int N>
__device__ __forceinline__ void cp_wait() { asm volatile("cp.async.wait_group %0;" :: "n"(N)); }

// ---------------------------------------------------------------------------
// Kernel 1: fused QKV 1x1x1 conv, TF32 MMA, cp.async double-buffered.
//   q[o,p] = sum_c wq[o,c]*x[c,p] + bq[o]   (same for k, v; shared X tile)
// ---------------------------------------------------------------------------
__global__ __launch_bounds__(256) void qkv_gemm(
    const float* __restrict__ x,
    const float* __restrict__ wq, const float* __restrict__ bq,
    const float* __restrict__ wk, const float* __restrict__ bk,
    const float* __restrict__ wv, const float* __restrict__ bv)
{
    __shared__ __align__(16) float sX [2][BK][BN + XPAD];   // [k][n]
    __shared__ __align__(16) float sWq[2][BM][BK + KPAD];   // [m][k]
    __shared__ __align__(16) float sWk[2][BM][BK + KPAD];
    __shared__ __align__(16) float sWv[2][BM][BK + KPAD];

    const int b    = blockIdx.z;
    const int m0   = blockIdx.y * BM;
    const int n0   = blockIdx.x * BN;
    const int tid  = threadIdx.x;
    const int warp = tid >> 5;
    const int lane = tid & 31;
    const int wm   = warp >> 2;          // 0..1
    const int wn   = warp & 3;           // 0..3
    const int g    = lane >> 2;          // 0..7
    const int t    = lane & 3;           // 0..3

    const float* xb = x + (size_t)b * CDIM * PDIM;

    // loader indices
    const int xl_kr0 = tid >> 5;               // 0..7   (i=0)
    const int xl_nc  = (tid & 31) * 4;
    const int wl_m   = tid & 63;               // 0..63
    const int wl_k4  = (tid >> 6) << 2;        // 0,4,8,12

    float accq[2][4][4] = {};
    float acck[2][4][4] = {};
    float accv[2][4][4] = {};

    // ---- prologue: load stage 0
    {
        const int k0 = 0;
        cp16(&sX[0][xl_kr0    ][xl_nc], &xb[(size_t)(k0 + xl_kr0    ) * PDIM + n0 + xl_nc]);
        cp16(&sX[0][xl_kr0 + 8][xl_nc], &xb[(size_t)(k0 + xl_kr0 + 8) * PDIM + n0 + xl_nc]);
        const size_t widx = (size_t)(m0 + wl_m) * CDIM + k0 + wl_k4;
        cp16(&sWq[0][wl_m][wl_k4], &wq[widx]);
        cp16(&sWk[0][wl_m][wl_k4], &wk[widx]);
        cp16(&sWv[0][wl_m][wl_k4], &wv[widx]);
        cp_commit();
    }

    const int NT = CDIM / BK;   // 16
    for (int it = 0; it < NT; it++) {
        const int st = it & 1;
        if (it + 1 < NT) {
            const int ns = st ^ 1;
            const int k0 = (it + 1) * BK;
            cp16(&sX[ns][xl_kr0    ][xl_nc], &xb[(size_t)(k0 + xl_kr0    ) * PDIM + n0 + xl_nc]);
            cp16(&sX[ns][xl_kr0 + 8][xl_nc], &xb[(size_t)(k0 + xl_kr0 + 8) * PDIM + n0 + xl_nc]);
            const size_t widx = (size_t)(m0 + wl_m) * CDIM + k0 + wl_k4;
            cp16(&sWq[ns][wl_m][wl_k4], &wq[widx]);
            cp16(&sWk[ns][wl_m][wl_k4], &wk[widx]);
            cp16(&sWv[ns][wl_m][wl_k4], &wv[widx]);
            cp_commit();
            cp_wait<1>();
        } else {
            cp_wait<0>();
        }
        __syncthreads();

        const float (*X)[BN + XPAD] = sX[st];
        const float (*Wq)[BK + KPAD] = sWq[st];
        const float (*Wk)[BK + KPAD] = sWk[st];
        const float (*Wv)[BK + KPAD] = sWv[st];

        #pragma unroll
        for (int ks = 0; ks < BK; ks += 8) {
            uint32_t bf[4][2];
            #pragma unroll
            for (int ni = 0; ni < 4; ni++) {
                int ncol = wn * 32 + ni * 8 + g;
                bf[ni][0] = to_tf32(X[ks + t    ][ncol]);
                bf[ni][1] = to_tf32(X[ks + t + 4][ncol]);
            }
            #pragma unroll
            for (int mat = 0; mat < 3; mat++) {
                const float (*W)[BK + KPAD] = (mat == 0) ? Wq : (mat == 1) ? Wk : Wv;
                float (*acc)[4][4]          = (mat == 0) ? accq : (mat == 1) ? acck : accv;
                #pragma unroll
                for (int mi = 0; mi < 2; mi++) {
                    int r = wm * 32 + mi * 16 + g;
                    uint32_t af[4];
                    af[0] = to_tf32(W[r    ][ks + t    ]);
                    af[1] = to_tf32(W[r + 8][ks + t    ]);
                    af[2] = to_tf32(W[r    ][ks + t + 4]);
                    af[3] = to_tf32(W[r + 8][ks + t + 4]);
                    #pragma unroll
                    for (int ni = 0; ni < 4; ni++)
                        mma_tf32(acc[mi][ni], af, bf[ni]);
                }
            }
        }
        __syncthreads();
    }

    // Epilogue: bias + store
    #pragma unroll
    for (int mi = 0; mi < 2; mi++) {
        #pragma unroll
        for (int rr = 0; rr < 2; rr++) {
            const int m  = m0 + wm * 32 + mi * 16 + g + rr * 8;
            const float biq = bq[m], bik = bk[m], biv = bv[m];
            const size_t rowbase = ((size_t)b * CDIM + m) * PDIM;
            #pragma unroll
            for (int ni = 0; ni < 4; ni++) {
                const size_t o = rowbase + n0 + wn * 32 + ni * 8 + t * 2;
                float2 vq = {accq[mi][ni][rr * 2] + biq, accq[mi][ni][rr * 2 + 1] + biq};
                float2 vk = {acck[mi][ni][rr * 2] + bik, acck[mi][ni][rr * 2 + 1] + bik};
                float2 vv = {accv[mi][ni][rr * 2] + biv, accv[mi][ni][rr * 2 + 1] + biv};
                *(float2*)&g_q[o] = vq;
                *(float2*)&g_k[o] = vk;
                *(float2*)&g_v[o] = vv;
            }
        }
    }
}

// ---------------------------------------------------------------------------
// Kernel 2: attention (the three reference branches are bitwise-identical
// reshapes since H==W==D -> compute one, scale by 3).
// 2 channels per block; S overlays the dead Q tile.
// ---------------------------------------------------------------------------
__global__ __launch_bounds__(256) void attn_kernel()
{
    __shared__ float sQ[2][40][41];   // Q, later S
    __shared__ float sK[2][40][41];
    __shared__ float sV[2][40][41];

    const int s1    = blockIdx.x;       // 0..39
    const int cpair = blockIdx.y;       // 0..15
    const int bh    = blockIdx.z;       // 0..15
    const int tid   = threadIdx.x;
    const int half  = tid >> 7;         // 0/1 -> channel within pair
    const int t2    = tid & 127;

    const int c = cpair * 2 + half;
    const size_t base = (size_t)(bh * HD + c) * PDIM + s1 * 1600;

    for (int e = t2; e < 1600; e += 128) {
        int r  = e / 40;
        int cc = e - r * 40;
        sQ[half][r][cc] = g_q[base + e];
        sK[half][r][cc] = g_k[base + e];
        sV[half][r][cc] = g_v[base + e];
    }
    __syncthreads();

    const float scale = 0.17677669529663687f;   // 32^-0.5
    const int i0 = (t2 / 10) * 4;
    const int j0 = (t2 % 10) * 4;

    // S = Q K^T * scale (into registers first; Q still being read by peers)
    float acc[4][4] = {};
    if (t2 < 100) {
        #pragma unroll 8
        for (int k = 0; k < 40; k++) {
            float qv[4], kv[4];
            #pragma unroll
            for (int a = 0; a < 4; a++) { qv[a] = sQ[half][i0 + a][k]; kv[a] = sK[half][j0 + a][k]; }
            #pragma unroll
            for (int a = 0; a < 4; a++)
                #pragma unroll
                for (int bb = 0; bb < 4; bb++)
                    acc[a][bb] = fmaf(qv[a], kv[bb], acc[a][bb]);
        }
    }
    __syncthreads();
    if (t2 < 100) {
        #pragma unroll
        for (int a = 0; a < 4; a++)
            #pragma unroll
            for (int bb = 0; bb < 4; bb++)
                sQ[half][i0 + a][j0 + bb] = acc[a][bb] * scale;   // S overwrites Q
    }
    __syncthreads();

    // row softmax
    if (t2 < 40) {
        float mx = -1e30f;
        #pragma unroll 8
        for (int j = 0; j < 40; j++) mx = fmaxf(mx, sQ[half][t2][j]);
        float sum = 0.0f;
        #pragma unroll 8
        for (int j = 0; j < 40; j++) {
            float ev = __expf(sQ[half][t2][j] - mx);
            sQ[half][t2][j] = ev;
            sum += ev;
        }
        const float inv = 1.0f / sum;
        #pragma unroll 8
        for (int j = 0; j < 40; j++) sQ[half][t2][j] *= inv;
    }
    __syncthreads();

    // O = 3 * (S V)
    if (t2 < 100) {
        float acc2[4][4] = {};
        #pragma unroll 8
        for (int k = 0; k < 40; k++) {
            float av[4], vv[4];
            #pragma unroll
            for (int a = 0; a < 4; a++) { av[a] = sQ[half][i0 + a][k]; vv[a] = sV[half][k][j0 + a]; }
            #pragma unroll
            for (int a = 0; a < 4; a++)
                #pragma unroll
                for (int bb = 0; bb < 4; bb++)
                    acc2[a][bb] = fmaf(av[a], vv[bb], acc2[a][bb]);
        }
        #pragma unroll
        for (int a = 0; a < 4; a++) {
            float4 o = {3.0f * acc2[a][0], 3.0f * acc2[a][1],
                        3.0f * acc2[a][2], 3.0f * acc2[a][3]};
            *(float4*)&g_attn[base + (size_t)(i0 + a) * 40 + j0] = o;
        }
    }
}

// ---------------------------------------------------------------------------
// Kernel 3: output projection, TF32 MMA + cp.async double buffer.
// ---------------------------------------------------------------------------
__global__ __launch_bounds__(256) void proj_gemm(
    const float* __restrict__ wp, const float* __restrict__ bp,
    float* __restrict__ out)
{
    __shared__ __align__(16) float sX[2][BK][BN + XPAD];
    __shared__ __align__(16) float sW[2][BM][BK + KPAD];

    const int b    = blockIdx.z;
    const int m0   = blockIdx.y * BM;
    const int n0   = blockIdx.x * BN;
    const int tid  = threadIdx.x;
    const int warp = tid >> 5;
    const int lane = tid & 31;
    const int wm   = warp >> 2;
    const int wn   = warp & 3;
    const int g    = lane >> 2;
    const int t    = lane & 3;

    const float* xb = g_attn + (size_t)b * CDIM * PDIM;

    const int xl_kr0 = tid >> 5;
    const int xl_nc  = (tid & 31) * 4;
    const int wl_m   = tid & 63;
    const int wl_k4  = (tid >> 6) << 2;

    float acc[2][4][4] = {};

    {
        cp16(&sX[0][xl_kr0    ][xl_nc], &xb[(size_t)(xl_kr0    ) * PDIM + n0 + xl_nc]);
        cp16(&sX[0][xl_kr0 + 8][xl_nc], &xb[(size_t)(xl_kr0 + 8) * PDIM + n0 + xl_nc]);
        cp16(&sW[0][wl_m][wl_k4], &wp[(size_t)(m0 + wl_m) * CDIM + wl_k4]);
        cp_commit();
    }

    const int NT = CDIM / BK;
    for (int it = 0; it < NT; it++) {
        const int st = it & 1;
        if (it + 1 < NT) {
            const int ns = st ^ 1;
            const int k0 = (it + 1) * BK;
            cp16(&sX[ns][xl_kr0    ][xl_nc], &xb[(size_t)(k0 + xl_kr0    ) * PDIM + n0 + xl_nc]);
            cp16(&sX[ns][xl_kr0 + 8][xl_nc], &xb[(size_t)(k0 + xl_kr0 + 8) * PDIM + n0 + xl_nc]);
            cp16(&sW[ns][wl_m][wl_k4], &wp[(size_t)(m0 + wl_m) * CDIM + k0 + wl_k4]);
            cp_commit();
            cp_wait<1>();
        } else {
            cp_wait<0>();
        }
        __syncthreads();

        const float (*X)[BN + XPAD] = sX[st];
        const float (*W)[BK + KPAD] = sW[st];

        #pragma unroll
        for (int ks = 0; ks < BK; ks += 8) {
            uint32_t bf[4][2];
            #pragma unroll
            for (int ni = 0; ni < 4; ni++) {
                int ncol = wn * 32 + ni * 8 + g;
                bf[ni][0] = to_tf32(X[ks + t    ][ncol]);
                bf[ni][1] = to_tf32(X[ks + t + 4][ncol]);
            }
            #pragma unroll
            for (int mi = 0; mi < 2; mi++) {
                int r = wm * 32 + mi * 16 + g;
                uint32_t af[4];
                af[0] = to_tf32(W[r    ][ks + t    ]);
                af[1] = to_tf32(W[r + 8][ks + t    ]);
                af[2] = to_tf32(W[r    ][ks + t + 4]);
                af[3] = to_tf32(W[r + 8][ks + t + 4]);
                #pragma unroll
                for (int ni = 0; ni < 4; ni++)
                    mma_tf32(acc[mi][ni], af, bf[ni]);
            }
        }
        __syncthreads();
    }

    #pragma unroll
    for (int mi = 0; mi < 2; mi++) {
        #pragma unroll
        for (int rr = 0; rr < 2; rr++) {
            const int m  = m0 + wm * 32 + mi * 16 + g + rr * 8;
            const float bi = bp[m];
            const size_t rowbase = ((size_t)b * CDIM + m) * PDIM;
            #pragma unroll
            for (int ni = 0; ni < 4; ni++) {
                const size_t o = rowbase + n0 + wn * 32 + ni * 8 + t * 2;
                float2 v = {acc[mi][ni][rr * 2] + bi, acc[mi][ni][rr * 2 + 1] + bi};
                *(float2*)&out[o] = v;
            }
        }
    }
}

// ---------------------------------------------------------------------------
extern "C" void kernel_launch(void* const* d_in, const int* in_sizes, int n_in,
                              void* d_out, int out_size)
{
    const float* x  = (const float*)d_in[0];
    const float* wq = (const float*)d_in[1];
    const float* bq = (const float*)d_in[2];
    const float* wk = (const float*)d_in[3];
    const float* bk = (const float*)d_in[4];
    const float* wv = (const float*)d_in[5];
    const float* bv = (const float*)d_in[6];
    const float* wp = (const float*)d_in[7];
    const float* bp = (const float*)d_in[8];
    float* out = (float*)d_out;

    dim3 gemm_grid(PDIM / BN, CDIM / BM, BATCH);     // 500 x 4 x 2
    qkv_gemm<<<gemm_grid, 256>>>(x, wq, bq, wk, bk, wv, bv);

    dim3 attn_grid(SDIM, HD / 2, BATCH * HEADS);     // 40 x 16 x 16
    attn_kernel<<<attn_grid, 256>>>();

    proj_gemm<<<gemm_grid, 256>>>(wp, bp, out);
}